// round 12
// baseline (speedup 1.0000x reference)
#include <cuda_runtime.h>
#include <cuda_bf16.h>
#include <cstdint>

// Backflow fused kernel, round 7: 2 pairs/thread weight amortization,
// 256 threads/CTA, 3 CTAs/SM. bf16 HFMA2 pair layer 1.
// B=512, N=32, D=256, K=8. 496 unordered pairs via tournament mapping.

#define NTHREADS 256

// ---- shared memory layout (float/uint32 slot offsets) ----
constexpr int OFF_X2  = 0;       // bf16x2 [128 dpairs][32 electrons]
constexpr int OFF_W1B = 4096;    // bf16x2 [256 d][20 fpairs] (80B rows, 16B-aligned)
constexpr int OFF_EB1 = 9216;    // 40
constexpr int OFF_W2  = 9256;    // 240
constexpr int OFF_EB2 = 9496;    // 6
constexpr int OFF_W3  = 9502;    // 6
constexpr int OFF_EB3 = 9508;    // 1 (pad to 9512)
constexpr int OFF_NW2 = 9512;    // 2025
constexpr int OFF_NB2 = 11537;   // 25 (pad to 11564)
constexpr int OFF_NW3 = 11564;   // 200
constexpr int OFF_NB3 = 11764;   // 8
constexpr int OFF_NB1 = 11772;   // 81 (pad to 11856)
constexpr int OFF_H1T = 11856;   // [81][33] = 2673 (pad to 14532)
constexpr int OFF_H2T = 14532;   // [25][33] = 825 (pad to 15360)
constexpr int OFF_WN  = 15360;   // [32][8]
constexpr int OFF_RS  = 15616;   // 96
constexpr int OFF_CRD = 15712;   // 24
constexpr int OFF_BFN = 15736;   // 96
constexpr int OFF_CUT = 15832;   // 32
constexpr int SMEM_FLOATS = 15864;
constexpr int SMEM_BYTES  = SMEM_FLOATS * 4;   // 63456 B -> 3 CTAs/SM

// shifted softplus: log(0.5*exp(x)+0.5). Fast MUFU path + large-x guard.
__device__ __forceinline__ float ssp(float x) {
    float r = __logf(fmaf(0.5f, __expf(x), 0.5f));
    return (x > 60.0f) ? (x - 0.69314718056f) : r;
}

__device__ __forceinline__ void scopy(float* dst, const float* src, int n, int tid) {
    for (int t = tid; t < n; t += NTHREADS) dst[t] = src[t];
}

__device__ __forceinline__ __nv_bfloat162 asbf2(uint32_t u) {
    return *reinterpret_cast<__nv_bfloat162*>(&u);
}

// tournament mapping: pair p -> (pi, pj); 31 rounds x 16 = all 496 unordered pairs
__device__ __forceinline__ void pair_of(int p, int& pi, int& pj) {
    int r = p >> 4, m = p & 15;
    int rr = (r < 31) ? r : 0;
    if (m == 0) { pi = 31; pj = rr; }
    else { pi = (rr + m) % 31; pj = (rr + 31 - m) % 31; }
}

// pair-MLP layers 2/3 + scatter-add for one pair
__device__ __forceinline__ void pair_tail(
    const __nv_bfloat162* __restrict__ acc, int pi, int pj, bool act,
    float* __restrict__ sm)
{
    float h2[6];
    #pragma unroll
    for (int c = 0; c < 6; ++c) h2[c] = sm[OFF_EB2 + c];
    #pragma unroll
    for (int q = 0; q < 20; ++q) {
        float h0 = ssp(__low2float(acc[q])  + sm[OFF_EB1 + 2 * q + 0]);
        float h1 = ssp(__high2float(acc[q]) + sm[OFF_EB1 + 2 * q + 1]);
        #pragma unroll
        for (int c = 0; c < 6; ++c) {
            h2[c] = fmaf(h0, sm[OFF_W2 + (2 * q + 0) * 6 + c], h2[c]);
            h2[c] = fmaf(h1, sm[OFF_W2 + (2 * q + 1) * 6 + c], h2[c]);
        }
    }
    float w = sm[OFF_EB3];
    #pragma unroll
    for (int c = 0; c < 6; ++c) w = fmaf(ssp(h2[c]), sm[OFF_W3 + c], w);
    if (!act) w = 0.0f;

    float dx = sm[OFF_RS + pi * 3 + 0] - sm[OFF_RS + pj * 3 + 0];
    float dy = sm[OFF_RS + pi * 3 + 1] - sm[OFF_RS + pj * 3 + 1];
    float dz = sm[OFF_RS + pi * 3 + 2] - sm[OFF_RS + pj * 3 + 2];
    float cx = w * dx, cy = w * dy, cz = w * dz;
    atomicAdd(&sm[OFF_BFN + pi * 3 + 0],  cx);
    atomicAdd(&sm[OFF_BFN + pi * 3 + 1],  cy);
    atomicAdd(&sm[OFF_BFN + pi * 3 + 2],  cz);
    atomicAdd(&sm[OFF_BFN + pj * 3 + 0], -cx);
    atomicAdd(&sm[OFF_BFN + pj * 3 + 1], -cy);
    atomicAdd(&sm[OFF_BFN + pj * 3 + 2], -cz);
}

__global__ __launch_bounds__(NTHREADS, 3)
void backflow_kernel(
    const float* __restrict__ rs, const float* __restrict__ xs, const float* __restrict__ coords,
    const float* __restrict__ ew1, const float* __restrict__ eb1,
    const float* __restrict__ ew2, const float* __restrict__ eb2,
    const float* __restrict__ ew3, const float* __restrict__ eb3,
    const float* __restrict__ nw1, const float* __restrict__ nb1,
    const float* __restrict__ nw2, const float* __restrict__ nb2,
    const float* __restrict__ nw3, const float* __restrict__ nb3,
    float* __restrict__ out)
{
    extern __shared__ float sm[];
    uint32_t* smu = reinterpret_cast<uint32_t*>(sm);
    const int b    = blockIdx.x;
    const int tid  = threadIdx.x;
    const int warp = tid >> 5, lane = tid & 31;

    // ---- stage ----
    const float* xsb = xs + b * 32 * 256;
    for (int m = tid; m < 32 * 128; m += NTHREADS) {
        int e = m >> 7, dp = m & 127;
        float2 v = *reinterpret_cast<const float2*>(xsb + e * 256 + 2 * dp);
        __nv_bfloat162 pv = __floats2bfloat162_rn(v.x, v.y);
        smu[OFF_X2 + dp * 32 + e] = *reinterpret_cast<uint32_t*>(&pv);
    }
    for (int m = tid; m < 256 * 20; m += NTHREADS) {
        int d = m / 20, q = m % 20;
        float2 v = *reinterpret_cast<const float2*>(ew1 + d * 40 + 2 * q);
        __nv_bfloat162 pv = __floats2bfloat162_rn(v.x, v.y);
        smu[OFF_W1B + d * 20 + q] = *reinterpret_cast<uint32_t*>(&pv);
    }
    scopy(sm + OFF_EB1, eb1, 40, tid);
    scopy(sm + OFF_W2,  ew2, 240, tid);
    scopy(sm + OFF_EB2, eb2, 6, tid);
    scopy(sm + OFF_W3,  ew3, 6, tid);
    scopy(sm + OFF_EB3, eb3, 1, tid);
    scopy(sm + OFF_NW2, nw2, 81 * 25, tid);
    scopy(sm + OFF_NB2, nb2, 25, tid);
    scopy(sm + OFF_NW3, nw3, 25 * 8, tid);
    scopy(sm + OFF_NB3, nb3, 8, tid);
    scopy(sm + OFF_NB1, nb1, 81, tid);
    scopy(sm + OFF_RS,  rs + b * 96, 96, tid);
    scopy(sm + OFF_CRD, coords, 24, tid);
    __syncthreads();

    // ---- nucleus MLP layer 1: 256 -> 81. lane = electron; warp owns 11 features.
    // NW1 via warp-uniform __ldg broadcast (L2-resident). ----
    {
        float ac[11]; int fi[11];
        #pragma unroll
        for (int c = 0; c < 11; ++c) {
            int f = warp + 8 * c; fi[c] = f;
            ac[c] = sm[OFF_NB1 + ((f < 81) ? f : 0)];
        }
        #pragma unroll 2
        for (int dp = 0; dp < 128; ++dp) {
            __nv_bfloat162 xv = asbf2(smu[OFF_X2 + dp * 32 + lane]);
            float xlo = __low2float(xv), xhi = __high2float(xv);
            #pragma unroll
            for (int c = 0; c < 11; ++c) {
                int fs = (fi[c] < 81) ? fi[c] : 0;
                ac[c] = fmaf(xlo, __ldg(nw1 + (2 * dp + 0) * 81 + fs), ac[c]);
                ac[c] = fmaf(xhi, __ldg(nw1 + (2 * dp + 1) * 81 + fs), ac[c]);
            }
        }
        #pragma unroll
        for (int c = 0; c < 11; ++c)
            if (fi[c] < 81) sm[OFF_H1T + fi[c] * 33 + lane] = ssp(ac[c]);
    }
    __syncthreads();

    // ---- nucleus layer 2: 81 -> 25. warp owns 4 columns. ----
    {
        float a[4]; int ci[4];
        #pragma unroll
        for (int u = 0; u < 4; ++u) {
            int c = warp + 8 * u; ci[u] = c;
            a[u] = sm[OFF_NB2 + ((c < 25) ? c : 0)];
        }
        #pragma unroll 3
        for (int f = 0; f < 81; ++f) {
            float h = sm[OFF_H1T + f * 33 + lane];
            #pragma unroll
            for (int u = 0; u < 4; ++u) {
                int cs = (ci[u] < 25) ? ci[u] : 0;
                a[u] = fmaf(h, sm[OFF_NW2 + f * 25 + cs], a[u]);
            }
        }
        #pragma unroll
        for (int u = 0; u < 4; ++u)
            if (ci[u] < 25) sm[OFF_H2T + ci[u] * 33 + lane] = ssp(a[u]);
    }
    __syncthreads();

    // ---- nucleus layer 3: 25 -> 8. warp = output k. ----
    {
        int k = warp;
        float a = sm[OFF_NB3 + k];
        #pragma unroll
        for (int c = 0; c < 25; ++c)
            a = fmaf(sm[OFF_H2T + c * 33 + lane], sm[OFF_NW3 + c * 8 + k], a);
        sm[OFF_WN + lane * 8 + k] = a;
    }
    __syncthreads();

    // ---- bf_nuc + cutoff (seeds the scatter-add accumulator) ----
    if (tid < 32) {
        const int i = tid;
        float rx = sm[OFF_RS + i * 3 + 0], ry = sm[OFF_RS + i * 3 + 1], rz = sm[OFF_RS + i * 3 + 2];
        float bx = 0.f, by = 0.f, bz = 0.f, cut = 1.f;
        #pragma unroll
        for (int k = 0; k < 8; ++k) {
            float dx = rx - sm[OFF_CRD + k * 3 + 0];
            float dy = ry - sm[OFF_CRD + k * 3 + 1];
            float dz = rz - sm[OFF_CRD + k * 3 + 2];
            float dist = sqrtf(dx * dx + dy * dy + dz * dz);
            float rr = dist * 2.0f;
            float cv = (rr < 0.5f) ? rr * rr * (6.0f - 8.0f * rr + 3.0f * rr * rr) : 1.0f;
            cut *= cv;
            float wk = sm[OFF_WN + i * 8 + k];
            bx = fmaf(wk, dx, bx); by = fmaf(wk, dy, by); bz = fmaf(wk, dz, bz);
        }
        sm[OFF_BFN + i * 3 + 0] = bx;
        sm[OFF_BFN + i * 3 + 1] = by;
        sm[OFF_BFN + i * 3 + 2] = bz;
        sm[OFF_CUT + i] = cut;
    }
    __syncthreads();

    // ---- pair MLP layer 1: 2 pairs per thread; weight LDS shared across both. ----
    const bool act = (tid < 248);
    const int p0 = act ? tid : 0;
    const int p1 = act ? tid + 248 : 1;
    int pi0, pj0, pi1, pj1;
    pair_of(p0, pi0, pj0);
    pair_of(p1, pi1, pj1);

    __nv_bfloat162 acc0[20], acc1[20];
    #pragma unroll
    for (int q = 0; q < 20; ++q) {
        acc0[q] = __floats2bfloat162_rn(0.f, 0.f);
        acc1[q] = __floats2bfloat162_rn(0.f, 0.f);
    }

    const uint32_t* X2 = smu + OFF_X2;

    #pragma unroll 2
    for (int dp = 0; dp < 128; ++dp) {
        __nv_bfloat162 pr0 = __hmul2(asbf2(X2[dp * 32 + pi0]), asbf2(X2[dp * 32 + pj0]));
        __nv_bfloat162 pr1 = __hmul2(asbf2(X2[dp * 32 + pi1]), asbf2(X2[dp * 32 + pj1]));
        __nv_bfloat162 pe0 = __low2bfloat162(pr0), po0 = __high2bfloat162(pr0);
        __nv_bfloat162 pe1 = __low2bfloat162(pr1), po1 = __high2bfloat162(pr1);
        const uint4* we = reinterpret_cast<const uint4*>(smu + OFF_W1B + (2 * dp + 0) * 20);
        const uint4* wo = reinterpret_cast<const uint4*>(smu + OFF_W1B + (2 * dp + 1) * 20);
        #pragma unroll
        for (int u = 0; u < 5; ++u) {
            uint4 w = we[u];
            acc0[4 * u + 0] = __hfma2(pe0, asbf2(w.x), acc0[4 * u + 0]);
            acc1[4 * u + 0] = __hfma2(pe1, asbf2(w.x), acc1[4 * u + 0]);
            acc0[4 * u + 1] = __hfma2(pe0, asbf2(w.y), acc0[4 * u + 1]);
            acc1[4 * u + 1] = __hfma2(pe1, asbf2(w.y), acc1[4 * u + 1]);
            acc0[4 * u + 2] = __hfma2(pe0, asbf2(w.z), acc0[4 * u + 2]);
            acc1[4 * u + 2] = __hfma2(pe1, asbf2(w.z), acc1[4 * u + 2]);
            acc0[4 * u + 3] = __hfma2(pe0, asbf2(w.w), acc0[4 * u + 3]);
            acc1[4 * u + 3] = __hfma2(pe1, asbf2(w.w), acc1[4 * u + 3]);
        }
        #pragma unroll
        for (int u = 0; u < 5; ++u) {
            uint4 w = wo[u];
            acc0[4 * u + 0] = __hfma2(po0, asbf2(w.x), acc0[4 * u + 0]);
            acc1[4 * u + 0] = __hfma2(po1, asbf2(w.x), acc1[4 * u + 0]);
            acc0[4 * u + 1] = __hfma2(po0, asbf2(w.y), acc0[4 * u + 1]);
            acc1[4 * u + 1] = __hfma2(po1, asbf2(w.y), acc1[4 * u + 1]);
            acc0[4 * u + 2] = __hfma2(po0, asbf2(w.z), acc0[4 * u + 2]);
            acc1[4 * u + 2] = __hfma2(po1, asbf2(w.z), acc1[4 * u + 2]);
            acc0[4 * u + 3] = __hfma2(po0, asbf2(w.w), acc0[4 * u + 3]);
            acc1[4 * u + 3] = __hfma2(po1, asbf2(w.w), acc1[4 * u + 3]);
        }
    }

    // ---- layers 2/3 + scatter-add for both pairs ----
    pair_tail(acc0, pi0, pj0, act, sm);
    pair_tail(acc1, pi1, pj1, act, sm);
    __syncthreads();

    // ---- final output ----
    if (tid < 96) {
        int i = tid / 3;
        float s = 1e-4f * sm[OFF_CUT + i];
        out[b * 96 + tid] = fmaf(s, sm[OFF_BFN + tid], sm[OFF_RS + tid]);
    }
}

extern "C" void kernel_launch(void* const* d_in, const int* in_sizes, int n_in,
                              void* d_out, int out_size)
{
    const float* rs     = (const float*)d_in[0];
    const float* xs     = (const float*)d_in[1];
    const float* coords = (const float*)d_in[2];
    const float* ew1    = (const float*)d_in[3];
    const float* eb1    = (const float*)d_in[4];
    const float* ew2    = (const float*)d_in[5];
    const float* eb2    = (const float*)d_in[6];
    const float* ew3    = (const float*)d_in[7];
    const float* eb3    = (const float*)d_in[8];
    const float* nw1    = (const float*)d_in[9];
    const float* nb1    = (const float*)d_in[10];
    const float* nw2    = (const float*)d_in[11];
    const float* nb2    = (const float*)d_in[12];
    const float* nw3    = (const float*)d_in[13];
    const float* nb3    = (const float*)d_in[14];
    float* out = (float*)d_out;

    int B = in_sizes[0] / 96;

    cudaFuncSetAttribute(backflow_kernel,
                         cudaFuncAttributeMaxDynamicSharedMemorySize, SMEM_BYTES);
    backflow_kernel<<<B, NTHREADS, SMEM_BYTES>>>(
        rs, xs, coords, ew1, eb1, ew2, eb2, ew3, eb3,
        nw1, nb1, nw2, nb2, nw3, nb3, out);
}

// round 14
// speedup vs baseline: 2.7071x; 2.7071x over previous
#include <cuda_runtime.h>
#include <cuda_bf16.h>
#include <cstdint>

// Backflow fused kernel, round 8: both layer-1 GEMMs on warp-level HMMA
// (mma.sync m16n8k16 bf16, f32 accum), fragments built in registers from smem.
// One CTA per batch. B=512, N=32, D=256, K=8. 496 unordered pairs.

#define NTHREADS 512

// ---- shared memory layout (u32/float slot offsets) ----
constexpr int OFF_X2    = 0;       // bf16x2 X [128 dp][33 pad] (bank-spread)
constexpr int OFF_W1P   = 4224;    // bf16x2 ew1 (k-even,k-odd) [128 dp][40 f]
constexpr int OFF_NW1P  = 9344;    // bf16x2 nw1 [128 dp][88 f] (zero-pad f>=81)
constexpr int OFF_EB1   = 20608;   // 40
constexpr int OFF_W2    = 20648;   // 240
constexpr int OFF_EB2   = 20888;   // 6
constexpr int OFF_W3    = 20894;   // 6
constexpr int OFF_EB3   = 20900;   // 1 (pad to 20904)
constexpr int OFF_NW2   = 20904;   // 2025
constexpr int OFF_NB2   = 22929;   // 25 (pad to 22956)
constexpr int OFF_NW3   = 22956;   // 200
constexpr int OFF_NB3   = 23156;   // 8
constexpr int OFF_NB1   = 23164;   // 81 (pad to 23248)
constexpr int OFF_H1T   = 23248;   // [81][33] = 2673 (pad to 25924)
constexpr int OFF_H2T   = 25924;   // [25][33] = 825 (pad to 26752)
constexpr int OFF_WN    = 26752;   // [32][8]
constexpr int OFF_RS    = 27008;   // 96
constexpr int OFF_CRD   = 27104;   // 24
constexpr int OFF_BFN   = 27128;   // 96
constexpr int OFF_CUT   = 27224;   // 32
constexpr int SMEM_FLOATS = 27256;
constexpr int SMEM_BYTES  = SMEM_FLOATS * 4;   // 109024 B -> 2 CTAs/SM

// shifted softplus: log(0.5*exp(x)+0.5). Fast MUFU path + large-x guard.
__device__ __forceinline__ float ssp(float x) {
    float r = __logf(fmaf(0.5f, __expf(x), 0.5f));
    return (x > 60.0f) ? (x - 0.69314718056f) : r;
}

__device__ __forceinline__ void scopy(float* dst, const float* src, int n, int tid) {
    for (int t = tid; t < n; t += NTHREADS) dst[t] = src[t];
}

__device__ __forceinline__ uint32_t hmul2u(uint32_t a, uint32_t b) {
    uint32_t r;
    asm("mul.bf16x2 %0, %1, %2;" : "=r"(r) : "r"(a), "r"(b));
    return r;
}

// m16n8k16 row.col f32.bf16.bf16.f32
__device__ __forceinline__ void mma_bf16(float* c,
                                         uint32_t a0, uint32_t a1, uint32_t a2, uint32_t a3,
                                         uint32_t b0, uint32_t b1) {
    asm volatile(
        "mma.sync.aligned.m16n8k16.row.col.f32.bf16.bf16.f32 "
        "{%0,%1,%2,%3}, {%4,%5,%6,%7}, {%8,%9}, {%0,%1,%2,%3};"
        : "+f"(c[0]), "+f"(c[1]), "+f"(c[2]), "+f"(c[3])
        : "r"(a0), "r"(a1), "r"(a2), "r"(a3), "r"(b0), "r"(b1));
}

// tournament mapping: pair p -> (pi, pj); 31 rounds x 16 = all 496 unordered pairs
__device__ __forceinline__ void pair_of(int p, int& pi, int& pj) {
    int r = p >> 4, m = p & 15;
    if (m == 0) { pi = 31; pj = r; }
    else { pi = (r + m) % 31; pj = (r + 31 - m) % 31; }
}

// layers 2/3 + atomics for one pair; thread holds features f=8t+2c,8t+2c+1 (t=0..4)
// in hv[t][0..1]. Quad (lanes with same g) reduces h2 via shfl_xor.
__device__ __forceinline__ void pair_tail_mma(
    const float hv[5][2], int c, int pi, int pj, float* __restrict__ sm)
{
    float h2[6];
    #pragma unroll
    for (int k = 0; k < 6; ++k) h2[k] = (c == 0) ? sm[OFF_EB2 + k] : 0.0f;
    #pragma unroll
    for (int t = 0; t < 5; ++t) {
        int f = 8 * t + 2 * c;
        float h0 = ssp(hv[t][0] + sm[OFF_EB1 + f + 0]);
        float h1 = ssp(hv[t][1] + sm[OFF_EB1 + f + 1]);
        #pragma unroll
        for (int k = 0; k < 6; ++k) {
            h2[k] = fmaf(h0, sm[OFF_W2 + (f + 0) * 6 + k], h2[k]);
            h2[k] = fmaf(h1, sm[OFF_W2 + (f + 1) * 6 + k], h2[k]);
        }
    }
    #pragma unroll
    for (int k = 0; k < 6; ++k) {
        h2[k] += __shfl_xor_sync(0xffffffffu, h2[k], 1);
        h2[k] += __shfl_xor_sync(0xffffffffu, h2[k], 2);
    }
    if (c == 0) {
        float w = sm[OFF_EB3];
        #pragma unroll
        for (int k = 0; k < 6; ++k) w = fmaf(ssp(h2[k]), sm[OFF_W3 + k], w);
        float dx = sm[OFF_RS + pi * 3 + 0] - sm[OFF_RS + pj * 3 + 0];
        float dy = sm[OFF_RS + pi * 3 + 1] - sm[OFF_RS + pj * 3 + 1];
        float dz = sm[OFF_RS + pi * 3 + 2] - sm[OFF_RS + pj * 3 + 2];
        float cx = w * dx, cy = w * dy, cz = w * dz;
        atomicAdd(&sm[OFF_BFN + pi * 3 + 0],  cx);
        atomicAdd(&sm[OFF_BFN + pi * 3 + 1],  cy);
        atomicAdd(&sm[OFF_BFN + pi * 3 + 2],  cz);
        atomicAdd(&sm[OFF_BFN + pj * 3 + 0], -cx);
        atomicAdd(&sm[OFF_BFN + pj * 3 + 1], -cy);
        atomicAdd(&sm[OFF_BFN + pj * 3 + 2], -cz);
    }
}

__global__ __launch_bounds__(NTHREADS, 2)
void backflow_kernel(
    const float* __restrict__ rs, const float* __restrict__ xs, const float* __restrict__ coords,
    const float* __restrict__ ew1, const float* __restrict__ eb1,
    const float* __restrict__ ew2, const float* __restrict__ eb2,
    const float* __restrict__ ew3, const float* __restrict__ eb3,
    const float* __restrict__ nw1, const float* __restrict__ nb1,
    const float* __restrict__ nw2, const float* __restrict__ nb2,
    const float* __restrict__ nw3, const float* __restrict__ nb3,
    float* __restrict__ out)
{
    extern __shared__ float sm[];
    uint32_t* smu = reinterpret_cast<uint32_t*>(sm);
    const int b    = blockIdx.x;
    const int tid  = threadIdx.x;
    const int warp = tid >> 5, lane = tid & 31;
    const int g = lane >> 2, c = lane & 3;   // mma group / thread-in-group

    // ---- stage ----
    const float* xsb = xs + b * 32 * 256;
    for (int m = tid; m < 32 * 128; m += NTHREADS) {
        int e = m >> 7, dp = m & 127;
        float2 v = *reinterpret_cast<const float2*>(xsb + e * 256 + 2 * dp);
        __nv_bfloat162 pv = __floats2bfloat162_rn(v.x, v.y);
        smu[OFF_X2 + dp * 33 + e] = *reinterpret_cast<uint32_t*>(&pv);
    }
    // W1P[dp][f] = (ew1[2dp][f], ew1[2dp+1][f])
    for (int m = tid; m < 128 * 40; m += NTHREADS) {
        int dp = m / 40, f = m % 40;
        __nv_bfloat162 pv = __floats2bfloat162_rn(ew1[(2 * dp + 0) * 40 + f],
                                                  ew1[(2 * dp + 1) * 40 + f]);
        smu[OFF_W1P + m] = *reinterpret_cast<uint32_t*>(&pv);
    }
    // NW1P[dp][f] = (nw1[2dp][f], nw1[2dp+1][f]), zero for f >= 81
    for (int m = tid; m < 128 * 88; m += NTHREADS) {
        int dp = m / 88, f = m % 88;
        uint32_t v = 0;
        if (f < 81) {
            __nv_bfloat162 pv = __floats2bfloat162_rn(nw1[(2 * dp + 0) * 81 + f],
                                                      nw1[(2 * dp + 1) * 81 + f]);
            v = *reinterpret_cast<uint32_t*>(&pv);
        }
        smu[OFF_NW1P + m] = v;
    }
    scopy(sm + OFF_EB1, eb1, 40, tid);
    scopy(sm + OFF_W2,  ew2, 240, tid);
    scopy(sm + OFF_EB2, eb2, 6, tid);
    scopy(sm + OFF_W3,  ew3, 6, tid);
    scopy(sm + OFF_EB3, eb3, 1, tid);
    scopy(sm + OFF_NW2, nw2, 81 * 25, tid);
    scopy(sm + OFF_NB2, nb2, 25, tid);
    scopy(sm + OFF_NW3, nw3, 25 * 8, tid);
    scopy(sm + OFF_NB3, nb3, 8, tid);
    scopy(sm + OFF_NB1, nb1, 81, tid);
    scopy(sm + OFF_RS,  rs + b * 96, 96, tid);
    scopy(sm + OFF_CRD, coords, 24, tid);
    __syncthreads();

    // ---- nucleus layer 1 via HMMA: H1[32x81] = X[32x256] @ NW1. 2x11 tiles. ----
    {
        #pragma unroll 1
        for (int tsel = 0; tsel < 2; ++tsel) {
            int t = warp + 16 * tsel;
            if (t >= 22) break;
            int mt = t / 11, nt = t % 11;
            int e0 = mt * 16 + g;
            int f0 = nt * 8;
            float acc[4] = {0.f, 0.f, 0.f, 0.f};
            #pragma unroll 4
            for (int ks = 0; ks < 16; ++ks) {
                int dp = ks * 8 + c;
                uint32_t a0 = smu[OFF_X2 + dp * 33 + e0];
                uint32_t a1 = smu[OFF_X2 + dp * 33 + e0 + 8];
                uint32_t a2 = smu[OFF_X2 + (dp + 4) * 33 + e0];
                uint32_t a3 = smu[OFF_X2 + (dp + 4) * 33 + e0 + 8];
                uint32_t b0 = smu[OFF_NW1P + dp * 88 + f0 + g];
                uint32_t b1 = smu[OFF_NW1P + (dp + 4) * 88 + f0 + g];
                mma_bf16(acc, a0, a1, a2, a3, b0, b1);
            }
            int f = f0 + 2 * c;
            if (f < 81) {
                sm[OFF_H1T + f * 33 + e0]     = ssp(acc[0] + sm[OFF_NB1 + f]);
                sm[OFF_H1T + f * 33 + e0 + 8] = ssp(acc[2] + sm[OFF_NB1 + f]);
            }
            if (f + 1 < 81) {
                sm[OFF_H1T + (f + 1) * 33 + e0]     = ssp(acc[1] + sm[OFF_NB1 + f + 1]);
                sm[OFF_H1T + (f + 1) * 33 + e0 + 8] = ssp(acc[3] + sm[OFF_NB1 + f + 1]);
            }
        }
    }
    __syncthreads();

    // ---- nucleus layer 2: 81 -> 25 (fp32) ----
    {
        int c0 = warp, c1 = warp + 16;
        float a0 = sm[OFF_NB2 + c0];
        float a1 = (c1 < 25) ? sm[OFF_NB2 + c1] : 0.0f;
        int c1s = (c1 < 25) ? c1 : 0;
        #pragma unroll 3
        for (int f = 0; f < 81; ++f) {
            float h = sm[OFF_H1T + f * 33 + lane];
            a0 = fmaf(h, sm[OFF_NW2 + f * 25 + c0], a0);
            a1 = fmaf(h, sm[OFF_NW2 + f * 25 + c1s], a1);
        }
        sm[OFF_H2T + c0 * 33 + lane] = ssp(a0);
        if (c1 < 25) sm[OFF_H2T + c1 * 33 + lane] = ssp(a1);
    }
    __syncthreads();

    // ---- nucleus layer 3: 25 -> 8 ----
    if (warp < 8) {
        int k = warp;
        float a = sm[OFF_NB3 + k];
        #pragma unroll
        for (int q = 0; q < 25; ++q)
            a = fmaf(sm[OFF_H2T + q * 33 + lane], sm[OFF_NW3 + q * 8 + k], a);
        sm[OFF_WN + lane * 8 + k] = a;
    }
    __syncthreads();

    // ---- bf_nuc + cutoff (seeds scatter-add accumulator) ----
    if (tid < 32) {
        const int i = tid;
        float rx = sm[OFF_RS + i * 3 + 0], ry = sm[OFF_RS + i * 3 + 1], rz = sm[OFF_RS + i * 3 + 2];
        float bx = 0.f, by = 0.f, bz = 0.f, cut = 1.f;
        #pragma unroll
        for (int k = 0; k < 8; ++k) {
            float dx = rx - sm[OFF_CRD + k * 3 + 0];
            float dy = ry - sm[OFF_CRD + k * 3 + 1];
            float dz = rz - sm[OFF_CRD + k * 3 + 2];
            float dist = sqrtf(dx * dx + dy * dy + dz * dz);
            float rr = dist * 2.0f;
            float cv = (rr < 0.5f) ? rr * rr * (6.0f - 8.0f * rr + 3.0f * rr * rr) : 1.0f;
            cut *= cv;
            float wk = sm[OFF_WN + i * 8 + k];
            bx = fmaf(wk, dx, bx); by = fmaf(wk, dy, by); bz = fmaf(wk, dz, bz);
        }
        sm[OFF_BFN + i * 3 + 0] = bx;
        sm[OFF_BFN + i * 3 + 1] = by;
        sm[OFF_BFN + i * 3 + 2] = bz;
        sm[OFF_CUT + i] = cut;
    }
    __syncthreads();

    // ---- pair layer 1 via HMMA: H[496x40] = P @ W1, P built in-register.
    // m-tile = tournament round (16 pairs); warp w does tiles w and w+16. ----
    {
        #pragma unroll 1
        for (int tsel = 0; tsel < 2; ++tsel) {
            int mt = warp + 16 * tsel;
            if (mt >= 31) break;
            int pilo, pjlo, pihi, pjhi;
            pair_of(mt * 16 + g, pilo, pjlo);
            pair_of(mt * 16 + g + 8, pihi, pjhi);

            float acc[5][4];
            #pragma unroll
            for (int t = 0; t < 5; ++t)
                #pragma unroll
                for (int q = 0; q < 4; ++q) acc[t][q] = 0.f;

            #pragma unroll 4
            for (int ks = 0; ks < 16; ++ks) {
                int dp = ks * 8 + c;
                const uint32_t* xr0 = smu + OFF_X2 + dp * 33;
                const uint32_t* xr1 = smu + OFF_X2 + (dp + 4) * 33;
                uint32_t a0 = hmul2u(xr0[pilo], xr0[pjlo]);
                uint32_t a1 = hmul2u(xr0[pihi], xr0[pjhi]);
                uint32_t a2 = hmul2u(xr1[pilo], xr1[pjlo]);
                uint32_t a3 = hmul2u(xr1[pihi], xr1[pjhi]);
                const uint32_t* w0 = smu + OFF_W1P + dp * 40 + g;
                const uint32_t* w1 = smu + OFF_W1P + (dp + 4) * 40 + g;
                #pragma unroll
                for (int t = 0; t < 5; ++t)
                    mma_bf16(acc[t], a0, a1, a2, a3, w0[t * 8], w1[t * 8]);
            }

            // epilogue: pair lo uses (acc[t][0],acc[t][1]), hi uses ([2],[3])
            float hv[5][2];
            #pragma unroll
            for (int t = 0; t < 5; ++t) { hv[t][0] = acc[t][0]; hv[t][1] = acc[t][1]; }
            pair_tail_mma(hv, c, pilo, pjlo, sm);
            #pragma unroll
            for (int t = 0; t < 5; ++t) { hv[t][0] = acc[t][2]; hv[t][1] = acc[t][3]; }
            pair_tail_mma(hv, c, pihi, pjhi, sm);
        }
    }
    __syncthreads();

    // ---- final output ----
    if (tid < 96) {
        int i = tid / 3;
        float s = 1e-4f * sm[OFF_CUT + i];
        out[b * 96 + tid] = fmaf(s, sm[OFF_BFN + tid], sm[OFF_RS + tid]);
    }
}

extern "C" void kernel_launch(void* const* d_in, const int* in_sizes, int n_in,
                              void* d_out, int out_size)
{
    const float* rs     = (const float*)d_in[0];
    const float* xs     = (const float*)d_in[1];
    const float* coords = (const float*)d_in[2];
    const float* ew1    = (const float*)d_in[3];
    const float* eb1    = (const float*)d_in[4];
    const float* ew2    = (const float*)d_in[5];
    const float* eb2    = (const float*)d_in[6];
    const float* ew3    = (const float*)d_in[7];
    const float* eb3    = (const float*)d_in[8];
    const float* nw1    = (const float*)d_in[9];
    const float* nb1    = (const float*)d_in[10];
    const float* nw2    = (const float*)d_in[11];
    const float* nb2    = (const float*)d_in[12];
    const float* nw3    = (const float*)d_in[13];
    const float* nb3    = (const float*)d_in[14];
    float* out = (float*)d_out;

    int B = in_sizes[0] / 96;

    cudaFuncSetAttribute(backflow_kernel,
                         cudaFuncAttributeMaxDynamicSharedMemorySize, SMEM_BYTES);
    backflow_kernel<<<B, NTHREADS, SMEM_BYTES>>>(
        rs, xs, coords, ew1, eb1, ew2, eb2, ew3, eb3,
        nw1, nb1, nw2, nb2, nw3, nb3, out);
}

// round 15
// speedup vs baseline: 3.0145x; 1.1136x over previous
#include <cuda_runtime.h>
#include <cuda_bf16.h>
#include <cstdint>

// Backflow fused kernel, round 9: HMMA layer-1 GEMMs + MMA-CHAINED pair epilogue
// (layers 2/3 fold in registers via a second m16n8k16 against padded W2),
// transposed nuc L2/L3 weights for vectorized broadcasts.
// One CTA per batch. B=512, N=32, D=256, K=8. 496 unordered pairs.

#define NTHREADS 512

// ---- shared memory layout (u32/float slot offsets) ----
constexpr int OFF_X2    = 0;       // bf16x2 X [128 dp][33 pad]
constexpr int OFF_W1P   = 4224;    // bf16x2 ew1 (k-even,k-odd) [128 dp][40 f]
constexpr int OFF_NW1P  = 9344;    // bf16x2 nw1 [128 dp][88 f] (zero-pad f>=81)
constexpr int OFF_EB1   = 20608;   // 40
constexpr int OFF_W2P   = 20648;   // bf16x2 W2 packed for chained MMA [3 ks][8 kp][8 n] = 192
constexpr int OFF_EB2P  = 20840;   // 8 (6 real + 2 zero)
constexpr int OFF_W3P   = 20848;   // 8 (6 real + 2 zero)
constexpr int OFF_EB3   = 20856;   // 1 (pad to 20860)
constexpr int OFF_NW2T  = 20860;   // nw2 transposed [25][84] = 2100 (16B-aligned base)
constexpr int OFF_NW3T  = 22960;   // nw3 transposed [8][28] = 224 (16B-aligned base)
constexpr int OFF_NB2   = 23184;   // 25
constexpr int OFF_NB3   = 23209;   // 8
constexpr int OFF_NB1   = 23217;   // 81 (pad to 23300)
constexpr int OFF_H1T   = 23300;   // [81][33] = 2673 (pad to 25976)
constexpr int OFF_H2T   = 25976;   // [25][33] = 825 (pad to 26804)
constexpr int OFF_WN    = 26804;   // [32][8]
constexpr int OFF_RS    = 27060;   // 96
constexpr int OFF_CRD   = 27156;   // 24
constexpr int OFF_BFN   = 27180;   // 96
constexpr int OFF_CUT   = 27276;   // 32
constexpr int SMEM_FLOATS = 27308;
constexpr int SMEM_BYTES  = SMEM_FLOATS * 4;   // 109232 B -> 2 CTAs/SM

// shifted softplus: log(0.5*exp(x)+0.5). Fast MUFU path + large-x guard.
__device__ __forceinline__ float ssp(float x) {
    float r = __logf(fmaf(0.5f, __expf(x), 0.5f));
    return (x > 60.0f) ? (x - 0.69314718056f) : r;
}

__device__ __forceinline__ void scopy(float* dst, const float* src, int n, int tid) {
    for (int t = tid; t < n; t += NTHREADS) dst[t] = src[t];
}

__device__ __forceinline__ uint32_t hmul2u(uint32_t a, uint32_t b) {
    uint32_t r;
    asm("mul.bf16x2 %0, %1, %2;" : "=r"(r) : "r"(a), "r"(b));
    return r;
}
__device__ __forceinline__ uint32_t packbf2(float lo, float hi) {
    __nv_bfloat162 v = __floats2bfloat162_rn(lo, hi);
    return *reinterpret_cast<uint32_t*>(&v);
}

// m16n8k16 row.col f32.bf16.bf16.f32
__device__ __forceinline__ void mma_bf16(float* c,
                                         uint32_t a0, uint32_t a1, uint32_t a2, uint32_t a3,
                                         uint32_t b0, uint32_t b1) {
    asm volatile(
        "mma.sync.aligned.m16n8k16.row.col.f32.bf16.bf16.f32 "
        "{%0,%1,%2,%3}, {%4,%5,%6,%7}, {%8,%9}, {%0,%1,%2,%3};"
        : "+f"(c[0]), "+f"(c[1]), "+f"(c[2]), "+f"(c[3])
        : "r"(a0), "r"(a1), "r"(a2), "r"(a3), "r"(b0), "r"(b1));
}

// tournament mapping: pair p -> (pi, pj); 31 rounds x 16 = all 496 unordered pairs
__device__ __forceinline__ void pair_of(int p, int& pi, int& pj) {
    int r = p >> 4, m = p & 15;
    if (m == 0) { pi = 31; pj = r; }
    else { pi = (r + m) % 31; pj = (r + 31 - m) % 31; }
}

__global__ __launch_bounds__(NTHREADS, 2)
void backflow_kernel(
    const float* __restrict__ rs, const float* __restrict__ xs, const float* __restrict__ coords,
    const float* __restrict__ ew1, const float* __restrict__ eb1,
    const float* __restrict__ ew2, const float* __restrict__ eb2,
    const float* __restrict__ ew3, const float* __restrict__ eb3,
    const float* __restrict__ nw1, const float* __restrict__ nb1,
    const float* __restrict__ nw2, const float* __restrict__ nb2,
    const float* __restrict__ nw3, const float* __restrict__ nb3,
    float* __restrict__ out)
{
    extern __shared__ float sm[];
    uint32_t* smu = reinterpret_cast<uint32_t*>(sm);
    const int b    = blockIdx.x;
    const int tid  = threadIdx.x;
    const int warp = tid >> 5, lane = tid & 31;
    const int g = lane >> 2, c = lane & 3;   // mma group / thread-in-group

    // ---- stage ----
    const float* xsb = xs + b * 32 * 256;
    for (int m = tid; m < 32 * 128; m += NTHREADS) {
        int e = m >> 7, dp = m & 127;
        float2 v = *reinterpret_cast<const float2*>(xsb + e * 256 + 2 * dp);
        smu[OFF_X2 + dp * 33 + e] = packbf2(v.x, v.y);
    }
    for (int m = tid; m < 128 * 40; m += NTHREADS) {
        int dp = m / 40, f = m % 40;
        smu[OFF_W1P + m] = packbf2(ew1[(2 * dp + 0) * 40 + f], ew1[(2 * dp + 1) * 40 + f]);
    }
    for (int m = tid; m < 128 * 88; m += NTHREADS) {
        int dp = m / 88, f = m % 88;
        uint32_t v = 0;
        if (f < 81)
            v = packbf2(nw1[(2 * dp + 0) * 81 + f], nw1[(2 * dp + 1) * 81 + f]);
        smu[OFF_NW1P + m] = v;
    }
    // W2P for chained epilogue MMA: [ks2][kp][n], k0 = 16*ks2+2*kp, zero-pad
    if (tid < 192) {
        int ks2 = tid >> 6, rem = tid & 63, kp = rem >> 3, n = rem & 7;
        int k0 = ks2 * 16 + 2 * kp;
        uint32_t v = 0;
        if (k0 < 40 && n < 6)
            v = packbf2(ew2[k0 * 6 + n], ew2[(k0 + 1) * 6 + n]);
        smu[OFF_W2P + tid] = v;
    }
    if (tid < 8) {
        sm[OFF_EB2P + tid] = (tid < 6) ? eb2[tid] : 0.0f;
        sm[OFF_W3P  + tid] = (tid < 6) ? ew3[tid] : 0.0f;
    }
    // transposed nuc weights for vectorized broadcasts
    for (int m = tid; m < 81 * 25; m += NTHREADS) {
        int f = m / 25, q = m % 25;
        sm[OFF_NW2T + q * 84 + f] = nw2[m];
    }
    for (int m = tid; m < 200; m += NTHREADS) {
        int q = m / 8, k = m % 8;
        sm[OFF_NW3T + k * 28 + q] = nw3[m];
    }
    scopy(sm + OFF_EB1, eb1, 40, tid);
    scopy(sm + OFF_EB3, eb3, 1, tid);
    scopy(sm + OFF_NB2, nb2, 25, tid);
    scopy(sm + OFF_NB3, nb3, 8, tid);
    scopy(sm + OFF_NB1, nb1, 81, tid);
    scopy(sm + OFF_RS,  rs + b * 96, 96, tid);
    scopy(sm + OFF_CRD, coords, 24, tid);
    __syncthreads();

    // ---- nucleus layer 1 via HMMA: H1[32x81] = X @ NW1. 2x11 tiles. ----
    {
        #pragma unroll 1
        for (int tsel = 0; tsel < 2; ++tsel) {
            int t = warp + 16 * tsel;
            if (t >= 22) break;
            int mt = t / 11, nt = t % 11;
            int e0 = mt * 16 + g;
            int f0 = nt * 8;
            float acc[4] = {0.f, 0.f, 0.f, 0.f};
            #pragma unroll 4
            for (int ks = 0; ks < 16; ++ks) {
                int dp = ks * 8 + c;
                uint32_t a0 = smu[OFF_X2 + dp * 33 + e0];
                uint32_t a1 = smu[OFF_X2 + dp * 33 + e0 + 8];
                uint32_t a2 = smu[OFF_X2 + (dp + 4) * 33 + e0];
                uint32_t a3 = smu[OFF_X2 + (dp + 4) * 33 + e0 + 8];
                uint32_t b0 = smu[OFF_NW1P + dp * 88 + f0 + g];
                uint32_t b1 = smu[OFF_NW1P + (dp + 4) * 88 + f0 + g];
                mma_bf16(acc, a0, a1, a2, a3, b0, b1);
            }
            int f = f0 + 2 * c;
            if (f < 81) {
                sm[OFF_H1T + f * 33 + e0]     = ssp(acc[0] + sm[OFF_NB1 + f]);
                sm[OFF_H1T + f * 33 + e0 + 8] = ssp(acc[2] + sm[OFF_NB1 + f]);
            }
            if (f + 1 < 81) {
                sm[OFF_H1T + (f + 1) * 33 + e0]     = ssp(acc[1] + sm[OFF_NB1 + f + 1]);
                sm[OFF_H1T + (f + 1) * 33 + e0 + 8] = ssp(acc[3] + sm[OFF_NB1 + f + 1]);
            }
        }
    }
    __syncthreads();

    // ---- nucleus layer 2: 81 -> 25, vectorized transposed weights ----
    {
        int c0 = warp, c1 = warp + 16;
        bool has1 = (c1 < 25);
        int c1s = has1 ? c1 : 0;
        float a0 = sm[OFF_NB2 + c0];
        float a1 = has1 ? sm[OFF_NB2 + c1] : 0.0f;
        const float* w0p = sm + OFF_NW2T + c0 * 84;
        const float* w1p = sm + OFF_NW2T + c1s * 84;
        #pragma unroll 5
        for (int fq = 0; fq < 20; ++fq) {
            float4 w0 = *reinterpret_cast<const float4*>(w0p + 4 * fq);
            float4 w1 = *reinterpret_cast<const float4*>(w1p + 4 * fq);
            float h0 = sm[OFF_H1T + (4 * fq + 0) * 33 + lane];
            float h1 = sm[OFF_H1T + (4 * fq + 1) * 33 + lane];
            float h2 = sm[OFF_H1T + (4 * fq + 2) * 33 + lane];
            float h3 = sm[OFF_H1T + (4 * fq + 3) * 33 + lane];
            a0 = fmaf(h0, w0.x, a0); a1 = fmaf(h0, w1.x, a1);
            a0 = fmaf(h1, w0.y, a0); a1 = fmaf(h1, w1.y, a1);
            a0 = fmaf(h2, w0.z, a0); a1 = fmaf(h2, w1.z, a1);
            a0 = fmaf(h3, w0.w, a0); a1 = fmaf(h3, w1.w, a1);
        }
        float ht = sm[OFF_H1T + 80 * 33 + lane];
        a0 = fmaf(ht, w0p[80], a0); a1 = fmaf(ht, w1p[80], a1);
        sm[OFF_H2T + c0 * 33 + lane] = ssp(a0);
        if (has1) sm[OFF_H2T + c1 * 33 + lane] = ssp(a1);
    }
    __syncthreads();

    // ---- nucleus layer 3: 25 -> 8, vectorized transposed weights ----
    if (warp < 8) {
        int k = warp;
        const float* wp = sm + OFF_NW3T + k * 28;
        float a = sm[OFF_NB3 + k];
        #pragma unroll
        for (int q = 0; q < 6; ++q) {
            float4 w = *reinterpret_cast<const float4*>(wp + 4 * q);
            a = fmaf(sm[OFF_H2T + (4 * q + 0) * 33 + lane], w.x, a);
            a = fmaf(sm[OFF_H2T + (4 * q + 1) * 33 + lane], w.y, a);
            a = fmaf(sm[OFF_H2T + (4 * q + 2) * 33 + lane], w.z, a);
            a = fmaf(sm[OFF_H2T + (4 * q + 3) * 33 + lane], w.w, a);
        }
        a = fmaf(sm[OFF_H2T + 24 * 33 + lane], wp[24], a);
        sm[OFF_WN + lane * 8 + k] = a;
    }
    __syncthreads();

    // ---- bf_nuc + cutoff (seeds scatter-add accumulator) ----
    if (tid < 32) {
        const int i = tid;
        float rx = sm[OFF_RS + i * 3 + 0], ry = sm[OFF_RS + i * 3 + 1], rz = sm[OFF_RS + i * 3 + 2];
        float bx = 0.f, by = 0.f, bz = 0.f, cut = 1.f;
        #pragma unroll
        for (int k = 0; k < 8; ++k) {
            float dx = rx - sm[OFF_CRD + k * 3 + 0];
            float dy = ry - sm[OFF_CRD + k * 3 + 1];
            float dz = rz - sm[OFF_CRD + k * 3 + 2];
            float dist = sqrtf(dx * dx + dy * dy + dz * dz);
            float rr = dist * 2.0f;
            float cv = (rr < 0.5f) ? rr * rr * (6.0f - 8.0f * rr + 3.0f * rr * rr) : 1.0f;
            cut *= cv;
            float wk = sm[OFF_WN + i * 8 + k];
            bx = fmaf(wk, dx, bx); by = fmaf(wk, dy, by); bz = fmaf(wk, dz, bz);
        }
        sm[OFF_BFN + i * 3 + 0] = bx;
        sm[OFF_BFN + i * 3 + 1] = by;
        sm[OFF_BFN + i * 3 + 2] = bz;
        sm[OFF_CUT + i] = cut;
    }
    __syncthreads();

    // ---- pair layer 1 via HMMA + chained MMA epilogue ----
    {
        #pragma unroll 1
        for (int tsel = 0; tsel < 2; ++tsel) {
            int mt = warp + 16 * tsel;
            if (mt >= 31) break;
            int pilo, pjlo, pihi, pjhi;
            pair_of(mt * 16 + g, pilo, pjlo);
            pair_of(mt * 16 + g + 8, pihi, pjhi);

            float acc[5][4];
            #pragma unroll
            for (int t = 0; t < 5; ++t)
                #pragma unroll
                for (int q = 0; q < 4; ++q) acc[t][q] = 0.f;

            #pragma unroll 4
            for (int ks = 0; ks < 16; ++ks) {
                int dp = ks * 8 + c;
                const uint32_t* xr0 = smu + OFF_X2 + dp * 33;
                const uint32_t* xr1 = smu + OFF_X2 + (dp + 4) * 33;
                uint32_t a0 = hmul2u(xr0[pilo], xr0[pjlo]);
                uint32_t a1 = hmul2u(xr0[pihi], xr0[pjhi]);
                uint32_t a2 = hmul2u(xr1[pilo], xr1[pjlo]);
                uint32_t a3 = hmul2u(xr1[pihi], xr1[pjhi]);
                const uint32_t* w0 = smu + OFF_W1P + dp * 40 + g;
                const uint32_t* w1 = smu + OFF_W1P + (dp + 4) * 40 + g;
                #pragma unroll
                for (int t = 0; t < 5; ++t)
                    mma_bf16(acc[t], a0, a1, a2, a3, w0[t * 8], w1[t * 8]);
            }

            // chained MMA: h2[16 pairs x 8] = ssp(h1 + eb1) @ W2pad. K=48 (3 steps).
            float h2d[4] = {0.f, 0.f, 0.f, 0.f};
            #pragma unroll
            for (int ks2 = 0; ks2 < 3; ++ks2) {
                int tl = 2 * ks2, th = 2 * ks2 + 1;
                float el0 = sm[OFF_EB1 + 16 * ks2 + 2 * c + 0];
                float el1 = sm[OFF_EB1 + 16 * ks2 + 2 * c + 1];
                uint32_t a0 = packbf2(ssp(acc[tl][0] + el0), ssp(acc[tl][1] + el1));
                uint32_t a1 = packbf2(ssp(acc[tl][2] + el0), ssp(acc[tl][3] + el1));
                uint32_t a2 = 0, a3 = 0;
                if (th < 5) {
                    float eh0 = sm[OFF_EB1 + 16 * ks2 + 8 + 2 * c + 0];
                    float eh1 = sm[OFF_EB1 + 16 * ks2 + 8 + 2 * c + 1];
                    a2 = packbf2(ssp(acc[th][0] + eh0), ssp(acc[th][1] + eh1));
                    a3 = packbf2(ssp(acc[th][2] + eh0), ssp(acc[th][3] + eh1));
                }
                uint32_t b0 = smu[OFF_W2P + (ks2 * 8 + c) * 8 + g];
                uint32_t b1 = smu[OFF_W2P + (ks2 * 8 + c + 4) * 8 + g];
                mma_bf16(h2d, a0, a1, a2, a3, b0, b1);
            }

            // layer 3 fold + butterfly reduce over c (quad)
            float e0 = sm[OFF_EB2P + 2 * c], e1 = sm[OFF_EB2P + 2 * c + 1];
            float w3a = sm[OFF_W3P + 2 * c], w3b = sm[OFF_W3P + 2 * c + 1];
            float wlo = ssp(h2d[0] + e0) * w3a + ssp(h2d[1] + e1) * w3b;
            float whi = ssp(h2d[2] + e0) * w3a + ssp(h2d[3] + e1) * w3b;
            wlo += __shfl_xor_sync(0xffffffffu, wlo, 1);
            wlo += __shfl_xor_sync(0xffffffffu, wlo, 2);
            whi += __shfl_xor_sync(0xffffffffu, whi, 1);
            whi += __shfl_xor_sync(0xffffffffu, whi, 2);

            if (c < 2) {
                float w = ((c == 0) ? wlo : whi) + sm[OFF_EB3];
                int pi = (c == 0) ? pilo : pihi;
                int pj = (c == 0) ? pjlo : pjhi;
                float dx = sm[OFF_RS + pi * 3 + 0] - sm[OFF_RS + pj * 3 + 0];
                float dy = sm[OFF_RS + pi * 3 + 1] - sm[OFF_RS + pj * 3 + 1];
                float dz = sm[OFF_RS + pi * 3 + 2] - sm[OFF_RS + pj * 3 + 2];
                float cx = w * dx, cy = w * dy, cz = w * dz;
                atomicAdd(&sm[OFF_BFN + pi * 3 + 0],  cx);
                atomicAdd(&sm[OFF_BFN + pi * 3 + 1],  cy);
                atomicAdd(&sm[OFF_BFN + pi * 3 + 2],  cz);
                atomicAdd(&sm[OFF_BFN + pj * 3 + 0], -cx);
                atomicAdd(&sm[OFF_BFN + pj * 3 + 1], -cy);
                atomicAdd(&sm[OFF_BFN + pj * 3 + 2], -cz);
            }
        }
    }
    __syncthreads();

    // ---- final output ----
    if (tid < 96) {
        int i = tid / 3;
        float s = 1e-4f * sm[OFF_CUT + i];
        out[b * 96 + tid] = fmaf(s, sm[OFF_BFN + tid], sm[OFF_RS + tid]);
    }
}

extern "C" void kernel_launch(void* const* d_in, const int* in_sizes, int n_in,
                              void* d_out, int out_size)
{
    const float* rs     = (const float*)d_in[0];
    const float* xs     = (const float*)d_in[1];
    const float* coords = (const float*)d_in[2];
    const float* ew1    = (const float*)d_in[3];
    const float* eb1    = (const float*)d_in[4];
    const float* ew2    = (const float*)d_in[5];
    const float* eb2    = (const float*)d_in[6];
    const float* ew3    = (const float*)d_in[7];
    const float* eb3    = (const float*)d_in[8];
    const float* nw1    = (const float*)d_in[9];
    const float* nb1    = (const float*)d_in[10];
    const float* nw2    = (const float*)d_in[11];
    const float* nb2    = (const float*)d_in[12];
    const float* nw3    = (const float*)d_in[13];
    const float* nb3    = (const float*)d_in[14];
    float* out = (float*)d_out;

    int B = in_sizes[0] / 96;

    cudaFuncSetAttribute(backflow_kernel,
                         cudaFuncAttributeMaxDynamicSharedMemorySize, SMEM_BYTES);
    backflow_kernel<<<B, NTHREADS, SMEM_BYTES>>>(
        rs, xs, coords, ew1, eb1, ew2, eb2, ew3, eb3,
        nw1, nb1, nw2, nb2, nw3, nb3, out);
}

// round 16
// speedup vs baseline: 4.4937x; 1.4907x over previous
#include <cuda_runtime.h>
#include <cuda_bf16.h>
#include <cstdint>

// Backflow fused kernel, round 10: LDS.64 row-pair fused operand tables
// (XQ/WQ/NWQ u64 layouts halve hot-loop LDS instruction count), NWQ region
// overlaid by H1T/H2T after nuc layer 1 (reg-buffered across sync).
// HMMA layer-1 GEMMs + chained-MMA pair epilogue as R15.
// One CTA per batch. B=512, N=32, D=256, K=8. 496 unordered pairs.

#define NTHREADS 512

// ---- u32-slot shared memory layout ----
constexpr int OFF_XQ   = 0;       // u64 XQ[64 q][stride 36] cols: 32 electrons
constexpr int OFF_WQ   = 4608;    // u64 WQ[64 q][stride 44] cols: 40 features
constexpr int OFF_NWQ  = 10240;   // u64 NWQ[64 q][stride 92] cols: 88 (zero-pad f>=81)
constexpr int OFF_H1T  = 10240;   // f32 [81][33] — OVERLAYS NWQ after nuc L1
constexpr int OFF_H2T  = 12916;   // f32 [25][33] — overlay region
constexpr int OFF_EB1  = 22016;   // 40
constexpr int OFF_W2P  = 22056;   // 192 (chained-MMA W2)
constexpr int OFF_EB2P = 22248;   // 8
constexpr int OFF_W3P  = 22256;   // 8
constexpr int OFF_EB3  = 22264;   // 1 (pad to 22268)
constexpr int OFF_NW2T = 22268;   // nw2^T [25][84]
constexpr int OFF_NW3T = 24368;   // nw3^T [8][28]
constexpr int OFF_NB2  = 24592;   // 25
constexpr int OFF_NB3  = 24617;   // 8
constexpr int OFF_NB1  = 24625;   // 81
constexpr int OFF_WN   = 24706;   // [32][8]
constexpr int OFF_RS   = 24962;   // 96
constexpr int OFF_CRD  = 25058;   // 24
constexpr int OFF_BFN  = 25082;   // 96
constexpr int OFF_CUT  = 25178;   // 32
constexpr int SMEM_FLOATS = 25212;
constexpr int SMEM_BYTES  = SMEM_FLOATS * 4;   // 100848 B -> 2 CTAs/SM

// shifted softplus: log(0.5*exp(x)+0.5). Fast MUFU path + large-x guard.
__device__ __forceinline__ float ssp(float x) {
    float r = __logf(fmaf(0.5f, __expf(x), 0.5f));
    return (x > 60.0f) ? (x - 0.69314718056f) : r;
}

__device__ __forceinline__ void scopy(float* dst, const float* src, int n, int tid) {
    for (int t = tid; t < n; t += NTHREADS) dst[t] = src[t];
}

__device__ __forceinline__ uint32_t hmul2u(uint32_t a, uint32_t b) {
    uint32_t r;
    asm("mul.bf16x2 %0, %1, %2;" : "=r"(r) : "r"(a), "r"(b));
    return r;
}
__device__ __forceinline__ uint32_t packbf2(float lo, float hi) {
    __nv_bfloat162 v = __floats2bfloat162_rn(lo, hi);
    return *reinterpret_cast<uint32_t*>(&v);
}

// m16n8k16 row.col f32.bf16.bf16.f32
__device__ __forceinline__ void mma_bf16(float* c,
                                         uint32_t a0, uint32_t a1, uint32_t a2, uint32_t a3,
                                         uint32_t b0, uint32_t b1) {
    asm volatile(
        "mma.sync.aligned.m16n8k16.row.col.f32.bf16.bf16.f32 "
        "{%0,%1,%2,%3}, {%4,%5,%6,%7}, {%8,%9}, {%0,%1,%2,%3};"
        : "+f"(c[0]), "+f"(c[1]), "+f"(c[2]), "+f"(c[3])
        : "r"(a0), "r"(a1), "r"(a2), "r"(a3), "r"(b0), "r"(b1));
}

// tournament mapping: pair p -> (pi, pj); 31 rounds x 16 = all 496 unordered pairs
__device__ __forceinline__ void pair_of(int p, int& pi, int& pj) {
    int r = p >> 4, m = p & 15;
    if (m == 0) { pi = 31; pj = r; }
    else { pi = (r + m) % 31; pj = (r + 31 - m) % 31; }
}

__global__ __launch_bounds__(NTHREADS, 2)
void backflow_kernel(
    const float* __restrict__ rs, const float* __restrict__ xs, const float* __restrict__ coords,
    const float* __restrict__ ew1, const float* __restrict__ eb1,
    const float* __restrict__ ew2, const float* __restrict__ eb2,
    const float* __restrict__ ew3, const float* __restrict__ eb3,
    const float* __restrict__ nw1, const float* __restrict__ nb1,
    const float* __restrict__ nw2, const float* __restrict__ nb2,
    const float* __restrict__ nw3, const float* __restrict__ nb3,
    float* __restrict__ out)
{
    extern __shared__ float sm[];
    uint32_t* smu = reinterpret_cast<uint32_t*>(sm);
    uint2* XQ  = reinterpret_cast<uint2*>(smu + OFF_XQ);
    uint2* WQ  = reinterpret_cast<uint2*>(smu + OFF_WQ);
    uint2* NWQ = reinterpret_cast<uint2*>(smu + OFF_NWQ);
    const int b    = blockIdx.x;
    const int tid  = threadIdx.x;
    const int warp = tid >> 5, lane = tid & 31;
    const int g = lane >> 2, c = lane & 3;   // mma group / thread-in-group

    // ---- stage ----
    const float* xsb = xs + b * 32 * 256;
    // XQ[q][e] = ( bf2(x[e][2dpL..]), bf2(x[e][2dpH..]) ), dpL=(q>>2)*8+(q&3), dpH=dpL+4
    for (int m = tid; m < 64 * 32; m += NTHREADS) {
        int e = m >> 6, q = m & 63;
        int dpL = ((q >> 2) << 3) + (q & 3);
        float2 lo = *reinterpret_cast<const float2*>(xsb + e * 256 + 2 * dpL);
        float2 hi = *reinterpret_cast<const float2*>(xsb + e * 256 + 2 * (dpL + 4));
        XQ[q * 36 + e] = make_uint2(packbf2(lo.x, lo.y), packbf2(hi.x, hi.y));
    }
    // WQ[q][f] = ( W1P[dpL][f], W1P[dpH][f] )
    for (int m = tid; m < 64 * 40; m += NTHREADS) {
        int q = m / 40, f = m % 40;
        int dpL = ((q >> 2) << 3) + (q & 3), dpH = dpL + 4;
        uint32_t vx = packbf2(ew1[(2 * dpL) * 40 + f], ew1[(2 * dpL + 1) * 40 + f]);
        uint32_t vy = packbf2(ew1[(2 * dpH) * 40 + f], ew1[(2 * dpH + 1) * 40 + f]);
        WQ[q * 44 + f] = make_uint2(vx, vy);
    }
    // NWQ[q][f] likewise from nw1; zero-pad f >= 81
    for (int m = tid; m < 64 * 88; m += NTHREADS) {
        int q = m / 88, f = m % 88;
        uint2 v = make_uint2(0, 0);
        if (f < 81) {
            int dpL = ((q >> 2) << 3) + (q & 3), dpH = dpL + 4;
            v.x = packbf2(nw1[(2 * dpL) * 81 + f], nw1[(2 * dpL + 1) * 81 + f]);
            v.y = packbf2(nw1[(2 * dpH) * 81 + f], nw1[(2 * dpH + 1) * 81 + f]);
        }
        NWQ[q * 92 + f] = v;
    }
    // W2P for chained epilogue MMA: [ks2][kp][n], zero-pad
    if (tid < 192) {
        int ks2 = tid >> 6, rem = tid & 63, kp = rem >> 3, n = rem & 7;
        int k0 = ks2 * 16 + 2 * kp;
        uint32_t v = 0;
        if (k0 < 40 && n < 6)
            v = packbf2(ew2[k0 * 6 + n], ew2[(k0 + 1) * 6 + n]);
        smu[OFF_W2P + tid] = v;
    }
    if (tid < 8) {
        sm[OFF_EB2P + tid] = (tid < 6) ? eb2[tid] : 0.0f;
        sm[OFF_W3P  + tid] = (tid < 6) ? ew3[tid] : 0.0f;
    }
    for (int m = tid; m < 81 * 25; m += NTHREADS) {
        int f = m / 25, q = m % 25;
        sm[OFF_NW2T + q * 84 + f] = nw2[m];
    }
    for (int m = tid; m < 200; m += NTHREADS) {
        int q = m / 8, k = m % 8;
        sm[OFF_NW3T + k * 28 + q] = nw3[m];
    }
    scopy(sm + OFF_EB1, eb1, 40, tid);
    scopy(sm + OFF_EB3, eb3, 1, tid);
    scopy(sm + OFF_NB2, nb2, 25, tid);
    scopy(sm + OFF_NB3, nb3, 8, tid);
    scopy(sm + OFF_NB1, nb1, 81, tid);
    scopy(sm + OFF_RS,  rs + b * 96, 96, tid);
    scopy(sm + OFF_CRD, coords, 24, tid);
    __syncthreads();

    // ---- nucleus layer 1 via HMMA (reg-buffered; H1T overlays NWQ after sync) ----
    float nr[2][4];
    bool  nv[2] = {false, false};
    {
        #pragma unroll 1
        for (int tsel = 0; tsel < 2; ++tsel) {
            int t = warp + 16 * tsel;
            if (t >= 22) break;
            nv[tsel] = true;
            int mt = t / 11, nt = t % 11;
            int e0 = mt * 16 + g;
            int f0 = nt * 8;
            float acc[4] = {0.f, 0.f, 0.f, 0.f};
            #pragma unroll 4
            for (int ks = 0; ks < 16; ++ks) {
                int q = ks * 4 + c;
                uint2 va = XQ[q * 36 + e0];
                uint2 vb = XQ[q * 36 + e0 + 8];
                uint2 w  = NWQ[q * 92 + f0 + g];
                mma_bf16(acc, va.x, vb.x, va.y, vb.y, w.x, w.y);
            }
            #pragma unroll
            for (int qq = 0; qq < 4; ++qq) nr[tsel][qq] = acc[qq];
        }
    }
    __syncthreads();   // all NWQ reads complete; overlay region now writable

    {
        #pragma unroll 1
        for (int tsel = 0; tsel < 2; ++tsel) {
            if (!nv[tsel]) break;
            int t = warp + 16 * tsel;
            int mt = t / 11, nt = t % 11;
            int e0 = mt * 16 + g;
            int f = nt * 8 + 2 * c;
            if (f < 81) {
                sm[OFF_H1T + f * 33 + e0]     = ssp(nr[tsel][0] + sm[OFF_NB1 + f]);
                sm[OFF_H1T + f * 33 + e0 + 8] = ssp(nr[tsel][2] + sm[OFF_NB1 + f]);
            }
            if (f + 1 < 81) {
                sm[OFF_H1T + (f + 1) * 33 + e0]     = ssp(nr[tsel][1] + sm[OFF_NB1 + f + 1]);
                sm[OFF_H1T + (f + 1) * 33 + e0 + 8] = ssp(nr[tsel][3] + sm[OFF_NB1 + f + 1]);
            }
        }
    }
    __syncthreads();

    // ---- nucleus layer 2: 81 -> 25, vectorized transposed weights ----
    {
        int c0 = warp, c1 = warp + 16;
        bool has1 = (c1 < 25);
        int c1s = has1 ? c1 : 0;
        float a0 = sm[OFF_NB2 + c0];
        float a1 = has1 ? sm[OFF_NB2 + c1] : 0.0f;
        const float* w0p = sm + OFF_NW2T + c0 * 84;
        const float* w1p = sm + OFF_NW2T + c1s * 84;
        #pragma unroll 5
        for (int fq = 0; fq < 20; ++fq) {
            float4 w0 = *reinterpret_cast<const float4*>(w0p + 4 * fq);
            float4 w1 = *reinterpret_cast<const float4*>(w1p + 4 * fq);
            float h0 = sm[OFF_H1T + (4 * fq + 0) * 33 + lane];
            float h1 = sm[OFF_H1T + (4 * fq + 1) * 33 + lane];
            float h2 = sm[OFF_H1T + (4 * fq + 2) * 33 + lane];
            float h3 = sm[OFF_H1T + (4 * fq + 3) * 33 + lane];
            a0 = fmaf(h0, w0.x, a0); a1 = fmaf(h0, w1.x, a1);
            a0 = fmaf(h1, w0.y, a0); a1 = fmaf(h1, w1.y, a1);
            a0 = fmaf(h2, w0.z, a0); a1 = fmaf(h2, w1.z, a1);
            a0 = fmaf(h3, w0.w, a0); a1 = fmaf(h3, w1.w, a1);
        }
        float ht = sm[OFF_H1T + 80 * 33 + lane];
        a0 = fmaf(ht, w0p[80], a0); a1 = fmaf(ht, w1p[80], a1);
        sm[OFF_H2T + c0 * 33 + lane] = ssp(a0);
        if (has1) sm[OFF_H2T + c1 * 33 + lane] = ssp(a1);
    }
    __syncthreads();

    // ---- nucleus layer 3: 25 -> 8, vectorized transposed weights ----
    if (warp < 8) {
        int k = warp;
        const float* wp = sm + OFF_NW3T + k * 28;
        float a = sm[OFF_NB3 + k];
        #pragma unroll
        for (int q = 0; q < 6; ++q) {
            float4 w = *reinterpret_cast<const float4*>(wp + 4 * q);
            a = fmaf(sm[OFF_H2T + (4 * q + 0) * 33 + lane], w.x, a);
            a = fmaf(sm[OFF_H2T + (4 * q + 1) * 33 + lane], w.y, a);
            a = fmaf(sm[OFF_H2T + (4 * q + 2) * 33 + lane], w.z, a);
            a = fmaf(sm[OFF_H2T + (4 * q + 3) * 33 + lane], w.w, a);
        }
        a = fmaf(sm[OFF_H2T + 24 * 33 + lane], wp[24], a);
        sm[OFF_WN + lane * 8 + k] = a;
    }
    __syncthreads();

    // ---- bf_nuc + cutoff (seeds scatter-add accumulator) ----
    if (tid < 32) {
        const int i = tid;
        float rx = sm[OFF_RS + i * 3 + 0], ry = sm[OFF_RS + i * 3 + 1], rz = sm[OFF_RS + i * 3 + 2];
        float bx = 0.f, by = 0.f, bz = 0.f, cut = 1.f;
        #pragma unroll
        for (int k = 0; k < 8; ++k) {
            float dx = rx - sm[OFF_CRD + k * 3 + 0];
            float dy = ry - sm[OFF_CRD + k * 3 + 1];
            float dz = rz - sm[OFF_CRD + k * 3 + 2];
            float dist = sqrtf(dx * dx + dy * dy + dz * dz);
            float rr = dist * 2.0f;
            float cv = (rr < 0.5f) ? rr * rr * (6.0f - 8.0f * rr + 3.0f * rr * rr) : 1.0f;
            cut *= cv;
            float wk = sm[OFF_WN + i * 8 + k];
            bx = fmaf(wk, dx, bx); by = fmaf(wk, dy, by); bz = fmaf(wk, dz, bz);
        }
        sm[OFF_BFN + i * 3 + 0] = bx;
        sm[OFF_BFN + i * 3 + 1] = by;
        sm[OFF_BFN + i * 3 + 2] = bz;
        sm[OFF_CUT + i] = cut;
    }
    __syncthreads();

    // ---- pair layer 1 via HMMA (LDS.64 fused loads) + chained MMA epilogue ----
    {
        #pragma unroll 1
        for (int tsel = 0; tsel < 2; ++tsel) {
            int mt = warp + 16 * tsel;
            if (mt >= 31) break;
            int pilo, pjlo, pihi, pjhi;
            pair_of(mt * 16 + g, pilo, pjlo);
            pair_of(mt * 16 + g + 8, pihi, pjhi);

            float acc[5][4];
            #pragma unroll
            for (int t = 0; t < 5; ++t)
                #pragma unroll
                for (int q = 0; q < 4; ++q) acc[t][q] = 0.f;

            #pragma unroll 4
            for (int ks = 0; ks < 16; ++ks) {
                int q = ks * 4 + c;
                const uint2* xq = XQ + q * 36;
                uint2 vli = xq[pilo];
                uint2 vlj = xq[pjlo];
                uint2 vhi = xq[pihi];
                uint2 vhj = xq[pjhi];
                uint32_t a0 = hmul2u(vli.x, vlj.x);   // row dp,   pair lo
                uint32_t a1 = hmul2u(vhi.x, vhj.x);   // row dp,   pair hi
                uint32_t a2 = hmul2u(vli.y, vlj.y);   // row dp+4, pair lo
                uint32_t a3 = hmul2u(vhi.y, vhj.y);   // row dp+4, pair hi
                const uint2* wq = WQ + q * 44 + g;
                #pragma unroll
                for (int t = 0; t < 5; ++t) {
                    uint2 w = wq[t * 8];
                    mma_bf16(acc[t], a0, a1, a2, a3, w.x, w.y);
                }
            }

            // chained MMA: h2[16 pairs x 8] = ssp(h1 + eb1) @ W2pad. K=48 (3 steps).
            float h2d[4] = {0.f, 0.f, 0.f, 0.f};
            #pragma unroll
            for (int ks2 = 0; ks2 < 3; ++ks2) {
                int tl = 2 * ks2, th = 2 * ks2 + 1;
                float el0 = sm[OFF_EB1 + 16 * ks2 + 2 * c + 0];
                float el1 = sm[OFF_EB1 + 16 * ks2 + 2 * c + 1];
                uint32_t a0 = packbf2(ssp(acc[tl][0] + el0), ssp(acc[tl][1] + el1));
                uint32_t a1 = packbf2(ssp(acc[tl][2] + el0), ssp(acc[tl][3] + el1));
                uint32_t a2 = 0, a3 = 0;
                if (th < 5) {
                    float eh0 = sm[OFF_EB1 + 16 * ks2 + 8 + 2 * c + 0];
                    float eh1 = sm[OFF_EB1 + 16 * ks2 + 8 + 2 * c + 1];
                    a2 = packbf2(ssp(acc[th][0] + eh0), ssp(acc[th][1] + eh1));
                    a3 = packbf2(ssp(acc[th][2] + eh0), ssp(acc[th][3] + eh1));
                }
                uint32_t b0 = smu[OFF_W2P + (ks2 * 8 + c) * 8 + g];
                uint32_t b1 = smu[OFF_W2P + (ks2 * 8 + c + 4) * 8 + g];
                mma_bf16(h2d, a0, a1, a2, a3, b0, b1);
            }

            // layer 3 fold + butterfly reduce over c (quad)
            float e0 = sm[OFF_EB2P + 2 * c], e1 = sm[OFF_EB2P + 2 * c + 1];
            float w3a = sm[OFF_W3P + 2 * c], w3b = sm[OFF_W3P + 2 * c + 1];
            float wlo = ssp(h2d[0] + e0) * w3a + ssp(h2d[1] + e1) * w3b;
            float whi = ssp(h2d[2] + e0) * w3a + ssp(h2d[3] + e1) * w3b;
            wlo += __shfl_xor_sync(0xffffffffu, wlo, 1);
            wlo += __shfl_xor_sync(0xffffffffu, wlo, 2);
            whi += __shfl_xor_sync(0xffffffffu, whi, 1);
            whi += __shfl_xor_sync(0xffffffffu, whi, 2);

            if (c < 2) {
                float w = ((c == 0) ? wlo : whi) + sm[OFF_EB3];
                int pi = (c == 0) ? pilo : pihi;
                int pj = (c == 0) ? pjlo : pjhi;
                float dx = sm[OFF_RS + pi * 3 + 0] - sm[OFF_RS + pj * 3 + 0];
                float dy = sm[OFF_RS + pi * 3 + 1] - sm[OFF_RS + pj * 3 + 1];
                float dz = sm[OFF_RS + pi * 3 + 2] - sm[OFF_RS + pj * 3 + 2];
                float cx = w * dx, cy = w * dy, cz = w * dz;
                atomicAdd(&sm[OFF_BFN + pi * 3 + 0],  cx);
                atomicAdd(&sm[OFF_BFN + pi * 3 + 1],  cy);
                atomicAdd(&sm[OFF_BFN + pi * 3 + 2],  cz);
                atomicAdd(&sm[OFF_BFN + pj * 3 + 0], -cx);
                atomicAdd(&sm[OFF_BFN + pj * 3 + 1], -cy);
                atomicAdd(&sm[OFF_BFN + pj * 3 + 2], -cz);
            }
        }
    }
    __syncthreads();

    // ---- final output ----
    if (tid < 96) {
        int i = tid / 3;
        float s = 1e-4f * sm[OFF_CUT + i];
        out[b * 96 + tid] = fmaf(s, sm[OFF_BFN + tid], sm[OFF_RS + tid]);
    }
}

extern "C" void kernel_launch(void* const* d_in, const int* in_sizes, int n_in,
                              void* d_out, int out_size)
{
    const float* rs     = (const float*)d_in[0];
    const float* xs     = (const float*)d_in[1];
    const float* coords = (const float*)d_in[2];
    const float* ew1    = (const float*)d_in[3];
    const float* eb1    = (const float*)d_in[4];
    const float* ew2    = (const float*)d_in[5];
    const float* eb2    = (const float*)d_in[6];
    const float* ew3    = (const float*)d_in[7];
    const float* eb3    = (const float*)d_in[8];
    const float* nw1    = (const float*)d_in[9];
    const float* nb1    = (const float*)d_in[10];
    const float* nw2    = (const float*)d_in[11];
    const float* nb2    = (const float*)d_in[12];
    const float* nw3    = (const float*)d_in[13];
    const float* nb3    = (const float*)d_in[14];
    float* out = (float*)d_out;

    int B = in_sizes[0] / 96;

    cudaFuncSetAttribute(backflow_kernel,
                         cudaFuncAttributeMaxDynamicSharedMemorySize, SMEM_BYTES);
    backflow_kernel<<<B, NTHREADS, SMEM_BYTES>>>(
        rs, xs, coords, ew1, eb1, ew2, eb2, ew3, eb3,
        nw1, nb1, nw2, nb2, nw3, nb3, out);
}

// round 17
// speedup vs baseline: 5.0913x; 1.1330x over previous
#include <cuda_runtime.h>
#include <cuda_bf16.h>
#include <cstdint>

// Backflow fused kernel, round 11: nucleus layer-2 moved onto HMMA
// (H1Q bf16 table written straight from nuc-L1 MMA regs; NW2Q fused-pair
// weight table), everything else as R16 (LDS.64 operand tables, chained
// pair epilogue). One CTA per batch. B=512, N=32, D=256, K=8.

#define NTHREADS 512

// ---- u32-slot shared memory layout ----
constexpr int OFF_XQ   = 0;       // u64 XQ[64 q][stride 36]: 32 electrons
constexpr int OFF_WQ   = 4608;    // u64 WQ[64 q][stride 44]: 40 features
constexpr int OFF_NWQ  = 10240;   // u64 NWQ[64 q][stride 92]: 88 (zero-pad f>=81)
constexpr int OFF_H1Q  = 10240;   // u64 H1Q[24 q][stride 36] — OVERLAYS NWQ after nuc L1
constexpr int OFF_H2T  = 11968;   // f32 [25][33] — overlay region
constexpr int OFF_EB1  = 22016;   // 40
constexpr int OFF_W2P  = 22056;   // 192 (chained-MMA W2)
constexpr int OFF_EB2P = 22248;   // 8
constexpr int OFF_W3P  = 22256;   // 8
constexpr int OFF_EB3  = 22264;   // 1 (pad to 22268)
constexpr int OFF_NW2Q = 22268;   // u64 NW2Q[24 q][stride 36]: 32 n (zero-pad n>=25)
constexpr int OFF_NW3T = 23996;   // nw3^T [8][28]
constexpr int OFF_NB2  = 24220;   // 25
constexpr int OFF_NB3  = 24245;   // 8
constexpr int OFF_NB1  = 24253;   // 81
constexpr int OFF_WN   = 24336;   // [32][8]
constexpr int OFF_RS   = 24592;   // 96
constexpr int OFF_CRD  = 24688;   // 24
constexpr int OFF_BFN  = 24712;   // 96
constexpr int OFF_CUT  = 24808;   // 32
constexpr int SMEM_FLOATS = 24840;
constexpr int SMEM_BYTES  = SMEM_FLOATS * 4;   // 99360 B -> 2 CTAs/SM

// shifted softplus: log(0.5*exp(x)+0.5). Fast MUFU path + large-x guard.
__device__ __forceinline__ float ssp(float x) {
    float r = __logf(fmaf(0.5f, __expf(x), 0.5f));
    return (x > 60.0f) ? (x - 0.69314718056f) : r;
}

__device__ __forceinline__ void scopy(float* dst, const float* src, int n, int tid) {
    for (int t = tid; t < n; t += NTHREADS) dst[t] = src[t];
}

__device__ __forceinline__ uint32_t hmul2u(uint32_t a, uint32_t b) {
    uint32_t r;
    asm("mul.bf16x2 %0, %1, %2;" : "=r"(r) : "r"(a), "r"(b));
    return r;
}
__device__ __forceinline__ uint32_t packbf2(float lo, float hi) {
    __nv_bfloat162 v = __floats2bfloat162_rn(lo, hi);
    return *reinterpret_cast<uint32_t*>(&v);
}

// m16n8k16 row.col f32.bf16.bf16.f32
__device__ __forceinline__ void mma_bf16(float* c,
                                         uint32_t a0, uint32_t a1, uint32_t a2, uint32_t a3,
                                         uint32_t b0, uint32_t b1) {
    asm volatile(
        "mma.sync.aligned.m16n8k16.row.col.f32.bf16.bf16.f32 "
        "{%0,%1,%2,%3}, {%4,%5,%6,%7}, {%8,%9}, {%0,%1,%2,%3};"
        : "+f"(c[0]), "+f"(c[1]), "+f"(c[2]), "+f"(c[3])
        : "r"(a0), "r"(a1), "r"(a2), "r"(a3), "r"(b0), "r"(b1));
}

// tournament mapping: pair p -> (pi, pj); 31 rounds x 16 = all 496 unordered pairs
__device__ __forceinline__ void pair_of(int p, int& pi, int& pj) {
    int r = p >> 4, m = p & 15;
    if (m == 0) { pi = 31; pj = r; }
    else { pi = (r + m) % 31; pj = (r + 31 - m) % 31; }
}

__global__ __launch_bounds__(NTHREADS, 2)
void backflow_kernel(
    const float* __restrict__ rs, const float* __restrict__ xs, const float* __restrict__ coords,
    const float* __restrict__ ew1, const float* __restrict__ eb1,
    const float* __restrict__ ew2, const float* __restrict__ eb2,
    const float* __restrict__ ew3, const float* __restrict__ eb3,
    const float* __restrict__ nw1, const float* __restrict__ nb1,
    const float* __restrict__ nw2, const float* __restrict__ nb2,
    const float* __restrict__ nw3, const float* __restrict__ nb3,
    float* __restrict__ out)
{
    extern __shared__ float sm[];
    uint32_t* smu = reinterpret_cast<uint32_t*>(sm);
    uint2* XQ   = reinterpret_cast<uint2*>(smu + OFF_XQ);
    uint2* WQ   = reinterpret_cast<uint2*>(smu + OFF_WQ);
    uint2* NWQ  = reinterpret_cast<uint2*>(smu + OFF_NWQ);
    uint2* H1Q  = reinterpret_cast<uint2*>(smu + OFF_H1Q);
    uint2* NW2Q = reinterpret_cast<uint2*>(smu + OFF_NW2Q);
    const int b    = blockIdx.x;
    const int tid  = threadIdx.x;
    const int warp = tid >> 5, lane = tid & 31;
    const int g = lane >> 2, c = lane & 3;   // mma group / thread-in-group

    // ---- stage ----
    const float* xsb = xs + b * 32 * 256;
    for (int m = tid; m < 64 * 32; m += NTHREADS) {
        int e = m >> 6, q = m & 63;
        int dpL = ((q >> 2) << 3) + (q & 3);
        float2 lo = *reinterpret_cast<const float2*>(xsb + e * 256 + 2 * dpL);
        float2 hi = *reinterpret_cast<const float2*>(xsb + e * 256 + 2 * (dpL + 4));
        XQ[q * 36 + e] = make_uint2(packbf2(lo.x, lo.y), packbf2(hi.x, hi.y));
    }
    for (int m = tid; m < 64 * 40; m += NTHREADS) {
        int q = m / 40, f = m % 40;
        int dpL = ((q >> 2) << 3) + (q & 3), dpH = dpL + 4;
        uint32_t vx = packbf2(ew1[(2 * dpL) * 40 + f], ew1[(2 * dpL + 1) * 40 + f]);
        uint32_t vy = packbf2(ew1[(2 * dpH) * 40 + f], ew1[(2 * dpH + 1) * 40 + f]);
        WQ[q * 44 + f] = make_uint2(vx, vy);
    }
    for (int m = tid; m < 64 * 88; m += NTHREADS) {
        int q = m / 88, f = m % 88;
        uint2 v = make_uint2(0, 0);
        if (f < 81) {
            int dpL = ((q >> 2) << 3) + (q & 3), dpH = dpL + 4;
            v.x = packbf2(nw1[(2 * dpL) * 81 + f], nw1[(2 * dpL + 1) * 81 + f]);
            v.y = packbf2(nw1[(2 * dpH) * 81 + f], nw1[(2 * dpH + 1) * 81 + f]);
        }
        NWQ[q * 92 + f] = v;
    }
    // NW2Q[q][n]: k-pairs of nw2 (81x25), zero-padded to k<96, n<32
    for (int m = tid; m < 24 * 32; m += NTHREADS) {
        int q = m >> 5, n = m & 31;
        int kpL = ((q >> 2) << 3) + (q & 3), kpH = kpL + 4;
        uint2 v = make_uint2(0, 0);
        if (n < 25) {
            int f0 = 2 * kpL, f1 = 2 * kpL + 1;
            float a = (f0 < 81) ? nw2[f0 * 25 + n] : 0.0f;
            float bb = (f1 < 81) ? nw2[f1 * 25 + n] : 0.0f;
            v.x = packbf2(a, bb);
            f0 = 2 * kpH; f1 = 2 * kpH + 1;
            a  = (f0 < 81) ? nw2[f0 * 25 + n] : 0.0f;
            bb = (f1 < 81) ? nw2[f1 * 25 + n] : 0.0f;
            v.y = packbf2(a, bb);
        }
        NW2Q[q * 36 + n] = v;
    }
    // W2P for chained epilogue MMA: [ks2][kp][n], zero-pad
    if (tid < 192) {
        int ks2 = tid >> 6, rem = tid & 63, kp = rem >> 3, n = rem & 7;
        int k0 = ks2 * 16 + 2 * kp;
        uint32_t v = 0;
        if (k0 < 40 && n < 6)
            v = packbf2(ew2[k0 * 6 + n], ew2[(k0 + 1) * 6 + n]);
        smu[OFF_W2P + tid] = v;
    }
    if (tid < 8) {
        sm[OFF_EB2P + tid] = (tid < 6) ? eb2[tid] : 0.0f;
        sm[OFF_W3P  + tid] = (tid < 6) ? ew3[tid] : 0.0f;
    }
    for (int m = tid; m < 200; m += NTHREADS) {
        int q = m / 8, k = m % 8;
        sm[OFF_NW3T + k * 28 + q] = nw3[m];
    }
    scopy(sm + OFF_EB1, eb1, 40, tid);
    scopy(sm + OFF_EB3, eb3, 1, tid);
    scopy(sm + OFF_NB2, nb2, 25, tid);
    scopy(sm + OFF_NB3, nb3, 8, tid);
    scopy(sm + OFF_NB1, nb1, 81, tid);
    scopy(sm + OFF_RS,  rs + b * 96, 96, tid);
    scopy(sm + OFF_CRD, coords, 24, tid);
    __syncthreads();

    // ---- nucleus layer 1 via HMMA (reg-buffered; H1Q overlays NWQ after sync) ----
    float nr[2][4];
    bool  nv[2] = {false, false};
    {
        #pragma unroll 1
        for (int tsel = 0; tsel < 2; ++tsel) {
            int t = warp + 16 * tsel;
            if (t >= 22) break;
            nv[tsel] = true;
            int mt = t / 11, nt = t % 11;
            int e0 = mt * 16 + g;
            int f0 = nt * 8;
            float acc[4] = {0.f, 0.f, 0.f, 0.f};
            #pragma unroll 4
            for (int ks = 0; ks < 16; ++ks) {
                int q = ks * 4 + c;
                uint2 va = XQ[q * 36 + e0];
                uint2 vb = XQ[q * 36 + e0 + 8];
                uint2 w  = NWQ[q * 92 + f0 + g];
                mma_bf16(acc, va.x, vb.x, va.y, vb.y, w.x, w.y);
            }
            #pragma unroll
            for (int qq = 0; qq < 4; ++qq) nr[tsel][qq] = acc[qq];
        }
    }
    __syncthreads();   // all NWQ reads complete; overlay region now writable

    // ---- write H1Q bf16-packed straight from MMA regs; zero pad cells ----
    {
        // pad cells: kp 44..47 -> (q = 20..23, slot y), all 32 electrons
        if (tid < 128) {
            int q = 20 + (tid >> 5), e = tid & 31;
            smu[OFF_H1Q + (q * 36 + e) * 2 + 1] = 0;
        }
        #pragma unroll 1
        for (int tsel = 0; tsel < 2; ++tsel) {
            if (!nv[tsel]) break;
            int t = warp + 16 * tsel;
            int mt = t / 11, nt = t % 11;
            int e0 = mt * 16 + g;
            int kp = nt * 4 + c;               // 0..43
            int f0 = 2 * kp, f1 = 2 * kp + 1;
            float h0a = (f0 < 81) ? ssp(nr[tsel][0] + sm[OFF_NB1 + f0]) : 0.0f;
            float h1a = (f1 < 81) ? ssp(nr[tsel][1] + sm[OFF_NB1 + f1]) : 0.0f;
            float h0b = (f0 < 81) ? ssp(nr[tsel][2] + sm[OFF_NB1 + f0]) : 0.0f;
            float h1b = (f1 < 81) ? ssp(nr[tsel][3] + sm[OFF_NB1 + f1]) : 0.0f;
            int blk = kp >> 3, rem = kp & 7;
            int slot = rem >> 2;
            int q = blk * 4 + (rem & 3);
            smu[OFF_H1Q + (q * 36 + e0) * 2 + slot]     = packbf2(h0a, h1a);
            smu[OFF_H1Q + (q * 36 + e0 + 8) * 2 + slot] = packbf2(h0b, h1b);
        }
    }
    __syncthreads();

    // ---- nucleus layer 2 via HMMA: H2[32x25(pad 32)] = ssp(H1) @ NW2. ----
    if (warp < 8) {
        int mt = warp >> 2, n0 = (warp & 3) * 8;
        int e0 = mt * 16 + g;
        float acc[4] = {0.f, 0.f, 0.f, 0.f};
        #pragma unroll
        for (int ks2 = 0; ks2 < 6; ++ks2) {
            int q = ks2 * 4 + c;
            uint2 va = H1Q[q * 36 + e0];
            uint2 vb = H1Q[q * 36 + e0 + 8];
            uint2 w  = NW2Q[q * 36 + n0 + g];
            mma_bf16(acc, va.x, vb.x, va.y, vb.y, w.x, w.y);
        }
        int n = n0 + 2 * c;
        if (n < 25) {
            float bb = sm[OFF_NB2 + n];
            sm[OFF_H2T + n * 33 + e0]     = ssp(acc[0] + bb);
            sm[OFF_H2T + n * 33 + e0 + 8] = ssp(acc[2] + bb);
        }
        if (n + 1 < 25) {
            float bb = sm[OFF_NB2 + n + 1];
            sm[OFF_H2T + (n + 1) * 33 + e0]     = ssp(acc[1] + bb);
            sm[OFF_H2T + (n + 1) * 33 + e0 + 8] = ssp(acc[3] + bb);
        }
    }
    __syncthreads();

    // ---- nucleus layer 3: 25 -> 8, vectorized transposed weights ----
    if (warp < 8) {
        int k = warp;
        const float* wp = sm + OFF_NW3T + k * 28;
        float a = sm[OFF_NB3 + k];
        #pragma unroll
        for (int q = 0; q < 6; ++q) {
            float4 w = *reinterpret_cast<const float4*>(wp + 4 * q);
            a = fmaf(sm[OFF_H2T + (4 * q + 0) * 33 + lane], w.x, a);
            a = fmaf(sm[OFF_H2T + (4 * q + 1) * 33 + lane], w.y, a);
            a = fmaf(sm[OFF_H2T + (4 * q + 2) * 33 + lane], w.z, a);
            a = fmaf(sm[OFF_H2T + (4 * q + 3) * 33 + lane], w.w, a);
        }
        a = fmaf(sm[OFF_H2T + 24 * 33 + lane], wp[24], a);
        sm[OFF_WN + lane * 8 + k] = a;
    }
    __syncthreads();

    // ---- bf_nuc + cutoff (seeds scatter-add accumulator) ----
    if (tid < 32) {
        const int i = tid;
        float rx = sm[OFF_RS + i * 3 + 0], ry = sm[OFF_RS + i * 3 + 1], rz = sm[OFF_RS + i * 3 + 2];
        float bx = 0.f, by = 0.f, bz = 0.f, cut = 1.f;
        #pragma unroll
        for (int k = 0; k < 8; ++k) {
            float dx = rx - sm[OFF_CRD + k * 3 + 0];
            float dy = ry - sm[OFF_CRD + k * 3 + 1];
            float dz = rz - sm[OFF_CRD + k * 3 + 2];
            float dist = sqrtf(dx * dx + dy * dy + dz * dz);
            float rr = dist * 2.0f;
            float cv = (rr < 0.5f) ? rr * rr * (6.0f - 8.0f * rr + 3.0f * rr * rr) : 1.0f;
            cut *= cv;
            float wk = sm[OFF_WN + i * 8 + k];
            bx = fmaf(wk, dx, bx); by = fmaf(wk, dy, by); bz = fmaf(wk, dz, bz);
        }
        sm[OFF_BFN + i * 3 + 0] = bx;
        sm[OFF_BFN + i * 3 + 1] = by;
        sm[OFF_BFN + i * 3 + 2] = bz;
        sm[OFF_CUT + i] = cut;
    }
    __syncthreads();

    // ---- pair layer 1 via HMMA (LDS.64 fused loads) + chained MMA epilogue ----
    {
        #pragma unroll 1
        for (int tsel = 0; tsel < 2; ++tsel) {
            int mt = warp + 16 * tsel;
            if (mt >= 31) break;
            int pilo, pjlo, pihi, pjhi;
            pair_of(mt * 16 + g, pilo, pjlo);
            pair_of(mt * 16 + g + 8, pihi, pjhi);

            float acc[5][4];
            #pragma unroll
            for (int t = 0; t < 5; ++t)
                #pragma unroll
                for (int q = 0; q < 4; ++q) acc[t][q] = 0.f;

            #pragma unroll 8
            for (int ks = 0; ks < 16; ++ks) {
                int q = ks * 4 + c;
                const uint2* xq = XQ + q * 36;
                uint2 vli = xq[pilo];
                uint2 vlj = xq[pjlo];
                uint2 vhi = xq[pihi];
                uint2 vhj = xq[pjhi];
                uint32_t a0 = hmul2u(vli.x, vlj.x);
                uint32_t a1 = hmul2u(vhi.x, vhj.x);
                uint32_t a2 = hmul2u(vli.y, vlj.y);
                uint32_t a3 = hmul2u(vhi.y, vhj.y);
                const uint2* wq = WQ + q * 44 + g;
                #pragma unroll
                for (int t = 0; t < 5; ++t) {
                    uint2 w = wq[t * 8];
                    mma_bf16(acc[t], a0, a1, a2, a3, w.x, w.y);
                }
            }

            // chained MMA: h2[16 pairs x 8] = ssp(h1 + eb1) @ W2pad. K=48 (3 steps).
            float h2d[4] = {0.f, 0.f, 0.f, 0.f};
            #pragma unroll
            for (int ks2 = 0; ks2 < 3; ++ks2) {
                int tl = 2 * ks2, th = 2 * ks2 + 1;
                float el0 = sm[OFF_EB1 + 16 * ks2 + 2 * c + 0];
                float el1 = sm[OFF_EB1 + 16 * ks2 + 2 * c + 1];
                uint32_t a0 = packbf2(ssp(acc[tl][0] + el0), ssp(acc[tl][1] + el1));
                uint32_t a1 = packbf2(ssp(acc[tl][2] + el0), ssp(acc[tl][3] + el1));
                uint32_t a2 = 0, a3 = 0;
                if (th < 5) {
                    float eh0 = sm[OFF_EB1 + 16 * ks2 + 8 + 2 * c + 0];
                    float eh1 = sm[OFF_EB1 + 16 * ks2 + 8 + 2 * c + 1];
                    a2 = packbf2(ssp(acc[th][0] + eh0), ssp(acc[th][1] + eh1));
                    a3 = packbf2(ssp(acc[th][2] + eh0), ssp(acc[th][3] + eh1));
                }
                uint32_t b0 = smu[OFF_W2P + (ks2 * 8 + c) * 8 + g];
                uint32_t b1 = smu[OFF_W2P + (ks2 * 8 + c + 4) * 8 + g];
                mma_bf16(h2d, a0, a1, a2, a3, b0, b1);
            }

            // layer 3 fold + butterfly reduce over c (quad)
            float e0 = sm[OFF_EB2P + 2 * c], e1 = sm[OFF_EB2P + 2 * c + 1];
            float w3a = sm[OFF_W3P + 2 * c], w3b = sm[OFF_W3P + 2 * c + 1];
            float wlo = ssp(h2d[0] + e0) * w3a + ssp(h2d[1] + e1) * w3b;
            float whi = ssp(h2d[2] + e0) * w3a + ssp(h2d[3] + e1) * w3b;
            wlo += __shfl_xor_sync(0xffffffffu, wlo, 1);
            wlo += __shfl_xor_sync(0xffffffffu, wlo, 2);
            whi += __shfl_xor_sync(0xffffffffu, whi, 1);
            whi += __shfl_xor_sync(0xffffffffu, whi, 2);

            if (c < 2) {
                float w = ((c == 0) ? wlo : whi) + sm[OFF_EB3];
                int pi = (c == 0) ? pilo : pihi;
                int pj = (c == 0) ? pjlo : pjhi;
                float dx = sm[OFF_RS + pi * 3 + 0] - sm[OFF_RS + pj * 3 + 0];
                float dy = sm[OFF_RS + pi * 3 + 1] - sm[OFF_RS + pj * 3 + 1];
                float dz = sm[OFF_RS + pi * 3 + 2] - sm[OFF_RS + pj * 3 + 2];
                float cx = w * dx, cy = w * dy, cz = w * dz;
                atomicAdd(&sm[OFF_BFN + pi * 3 + 0],  cx);
                atomicAdd(&sm[OFF_BFN + pi * 3 + 1],  cy);
                atomicAdd(&sm[OFF_BFN + pi * 3 + 2],  cz);
                atomicAdd(&sm[OFF_BFN + pj * 3 + 0], -cx);
                atomicAdd(&sm[OFF_BFN + pj * 3 + 1], -cy);
                atomicAdd(&sm[OFF_BFN + pj * 3 + 2], -cz);
            }
        }
    }
    __syncthreads();

    // ---- final output ----
    if (tid < 96) {
        int i = tid / 3;
        float s = 1e-4f * sm[OFF_CUT + i];
        out[b * 96 + tid] = fmaf(s, sm[OFF_BFN + tid], sm[OFF_RS + tid]);
    }
}

extern "C" void kernel_launch(void* const* d_in, const int* in_sizes, int n_in,
                              void* d_out, int out_size)
{
    const float* rs     = (const float*)d_in[0];
    const float* xs     = (const float*)d_in[1];
    const float* coords = (const float*)d_in[2];
    const float* ew1    = (const float*)d_in[3];
    const float* eb1    = (const float*)d_in[4];
    const float* ew2    = (const float*)d_in[5];
    const float* eb2    = (const float*)d_in[6];
    const float* ew3    = (const float*)d_in[7];
    const float* eb3    = (const float*)d_in[8];
    const float* nw1    = (const float*)d_in[9];
    const float* nb1    = (const float*)d_in[10];
    const float* nw2    = (const float*)d_in[11];
    const float* nb2    = (const float*)d_in[12];
    const float* nw3    = (const float*)d_in[13];
    const float* nb3    = (const float*)d_in[14];
    float* out = (float*)d_out;

    int B = in_sizes[0] / 96;

    cudaFuncSetAttribute(backflow_kernel,
                         cudaFuncAttributeMaxDynamicSharedMemorySize, SMEM_BYTES);
    backflow_kernel<<<B, NTHREADS, SMEM_BYTES>>>(
        rs, xs, coords, ew1, eb1, ew2, eb2, ew3, eb3,
        nw1, nb1, nw2, nb2, nw3, nb3, out);
}